// round 14
// baseline (speedup 1.0000x reference)
#include <cuda_runtime.h>
#include <cuda_bf16.h>

#define NN 100000
#define NE 3200000
#define NG 1024
#define D  128
#define BN_EPS 1e-5f
#define NPAD (NN + 128)

// ---------------- scratch (static device globals; no runtime alloc) ----------
__device__ __nv_bfloat16 g_aggh[(size_t)NPAD * D];  // split(agg) hi plane
__device__ __nv_bfloat16 g_aggl[(size_t)NPAD * D];  // split(agg) lo plane
__device__ float g_h1 [(size_t)NN * D];
__device__ float g_hA [(size_t)NN * D];
__device__ float g_hB [(size_t)NN * D];
__device__ int   g_rowptr[NN + 1];
__device__ int   g_cnt[NN];
__device__ int   g_csrc[NE];
__device__ __nv_bfloat16 g_wh[8 * D * D];   // pre-split weights (2l=W1, 2l+1=W2)
__device__ __nv_bfloat16 g_wl[8 * D * D];
__device__ float g_stats2[256 * 32];        // one 128B line per scalar
__device__ float g_scale[D];
__device__ float g_shift[D];
__device__ float g_pooled[(size_t)NG * 4 * D];
__device__ int   g_gstart[NG + 1];
__device__ float g_c1[NG * D];
__device__ float g_c2[NG * (D / 2)];

// ---------------- mma/ldmatrix helpers ----------------------------------------
__device__ __forceinline__ unsigned smem_u32(const void* p) {
    return (unsigned)__cvta_generic_to_shared(p);
}
__device__ __forceinline__ void ldsm_x4(unsigned addr, unsigned& r0, unsigned& r1,
                                        unsigned& r2, unsigned& r3) {
    asm volatile("ldmatrix.sync.aligned.m8n8.x4.shared.b16 {%0,%1,%2,%3}, [%4];"
                 : "=r"(r0), "=r"(r1), "=r"(r2), "=r"(r3) : "r"(addr));
}
__device__ __forceinline__ void ldsm_x4t(unsigned addr, unsigned& r0, unsigned& r1,
                                         unsigned& r2, unsigned& r3) {
    asm volatile("ldmatrix.sync.aligned.m8n8.x4.trans.shared.b16 {%0,%1,%2,%3}, [%4];"
                 : "=r"(r0), "=r"(r1), "=r"(r2), "=r"(r3) : "r"(addr));
}
__device__ __forceinline__ void mma_bf16(float* d, const unsigned* a, const unsigned* b) {
    asm volatile(
        "mma.sync.aligned.m16n8k16.row.col.f32.bf16.bf16.f32 "
        "{%0,%1,%2,%3}, {%4,%5,%6,%7}, {%8,%9}, {%0,%1,%2,%3};"
        : "+f"(d[0]), "+f"(d[1]), "+f"(d[2]), "+f"(d[3])
        : "r"(a[0]), "r"(a[1]), "r"(a[2]), "r"(a[3]), "r"(b[0]), "r"(b[1]));
}
__device__ __forceinline__ void split_bf16(float v, __nv_bfloat16& h, __nv_bfloat16& l) {
    h = __float2bfloat16_rn(v);
    l = __float2bfloat16_rn(v - __bfloat162float(h));
}

// ---------------- weight pre-split ---------------------------------------------
__global__ void k_splitW(const float* __restrict__ w1, const float* __restrict__ w2,
                         const float* __restrict__ lw1, const float* __restrict__ lw2) {
    int f = blockIdx.x * blockDim.x + threadIdx.x;   // 32768 float4s
    int wi = f >> 12;
    int of = f & 4095;
    const float* srcs[8] = { w1, w2, lw1, lw2, lw1 + D * D, lw2 + D * D,
                             lw1 + 2 * D * D, lw2 + 2 * D * D };
    float4 v = *(const float4*)(srcs[wi] + of * 4);
    __nv_bfloat16 h0, h1, h2, h3, l0, l1, l2, l3;
    split_bf16(v.x, h0, l0); split_bf16(v.y, h1, l1);
    split_bf16(v.z, h2, l2); split_bf16(v.w, h3, l3);
    __nv_bfloat162* ph = (__nv_bfloat162*)(g_wh + (size_t)wi * D * D + of * 4);
    __nv_bfloat162* pl = (__nv_bfloat162*)(g_wl + (size_t)wi * D * D + of * 4);
    ph[0] = __nv_bfloat162(h0, h1); ph[1] = __nv_bfloat162(h2, h3);
    pl[0] = __nv_bfloat162(l0, l1); pl[1] = __nv_bfloat162(l2, l3);
}

// ---------------- CSR build ---------------------------------------------------
__global__ void k_hist(const int* __restrict__ dst) {
    for (int e = blockIdx.x * blockDim.x + threadIdx.x; e < NE; e += gridDim.x * blockDim.x)
        atomicAdd(&g_cnt[dst[e]], 1);
}

__global__ void k_scan(const int* __restrict__ batch) {
    __shared__ int totals[1024];
    int t = threadIdx.x;
    const int CH = (NN + 1023) / 1024;
    int start = t * CH;
    int end   = start + CH; if (end > NN) end = NN;
    int s = 0;
    for (int i = start; i < end; i++) s += g_cnt[i];
    totals[t] = s;
    __syncthreads();
    if (t == 0) {
        int run = 0;
        for (int i = 0; i < 1024; i++) { int v = totals[i]; totals[i] = run; run += v; }
        g_rowptr[NN] = run;
    }
    __syncthreads();
    int run = totals[t];
    for (int i = start; i < end; i++) {
        g_rowptr[i] = run; run += g_cnt[i];
        g_cnt[i] = 0;
    }
    {
        int lo = 0, hi = NN;
        while (lo < hi) { int mid = (lo + hi) >> 1; if (batch[mid] < t) lo = mid + 1; else hi = mid; }
        g_gstart[t] = lo;
        if (t == 0) g_gstart[NG] = NN;
    }
}

__global__ void k_scatter(const int* __restrict__ src, const int* __restrict__ dst) {
    for (int e = blockIdx.x * blockDim.x + threadIdx.x; e < NE; e += gridDim.x * blockDim.x) {
        int d = dst[e];
        int pos = g_rowptr[d] + atomicAdd(&g_cnt[d], 1);
        g_csrc[pos] = src[e];
    }
}

// ---------------- aggregation + bf16 split epilogue ---------------------------
__global__ void k_agg(const float* __restrict__ h) {
    int node = blockIdx.x * 4 + (threadIdx.x >> 5);
    int lane = threadIdx.x & 31;
    if (node >= NN) return;
    int e0 = g_rowptr[node], e1 = g_rowptr[node + 1];

    float4 acc = *(const float4*)(h + (size_t)node * D + lane * 4);
    int e = e0;
    for (; e + 4 <= e1; e += 4) {
        int s0 = g_csrc[e], s1 = g_csrc[e + 1], s2 = g_csrc[e + 2], s3 = g_csrc[e + 3];
        float4 v0 = *(const float4*)(h + (size_t)s0 * D + lane * 4);
        float4 v1 = *(const float4*)(h + (size_t)s1 * D + lane * 4);
        float4 v2 = *(const float4*)(h + (size_t)s2 * D + lane * 4);
        float4 v3 = *(const float4*)(h + (size_t)s3 * D + lane * 4);
        acc.x += (v0.x + v1.x) + (v2.x + v3.x);
        acc.y += (v0.y + v1.y) + (v2.y + v3.y);
        acc.z += (v0.z + v1.z) + (v2.z + v3.z);
        acc.w += (v0.w + v1.w) + (v2.w + v3.w);
    }
    for (; e < e1; e++) {
        float4 v = *(const float4*)(h + (size_t)g_csrc[e] * D + lane * 4);
        acc.x += v.x; acc.y += v.y; acc.z += v.z; acc.w += v.w;
    }
    __nv_bfloat16 h0, h1, h2, h3, l0, l1, l2, l3;
    split_bf16(acc.x, h0, l0); split_bf16(acc.y, h1, l1);
    split_bf16(acc.z, h2, l2); split_bf16(acc.w, h3, l3);
    __nv_bfloat162* ph = (__nv_bfloat162*)(g_aggh + (size_t)node * D + lane * 4);
    __nv_bfloat162* pl = (__nv_bfloat162*)(g_aggl + (size_t)node * D + lane * 4);
    ph[0] = __nv_bfloat162(h0, h1); ph[1] = __nv_bfloat162(h2, h3);
    pl[0] = __nv_bfloat162(l0, l1); pl[1] = __nv_bfloat162(l2, l3);
}

// ---------------- full-K tensor-core GEMM, 64x128 tile, 2 CTAs/SM -------------
// 256 threads (8 warps, warp tile 32x32: wm in {0,32}, wn in {0,32,64,96}),
// full K=128 in smem, single stage + single sync, 3-term bf16-split mma.
// MODE 0: A = pre-split g_aggh/g_aggl; fused BN stats; no output relu.
// MODE 1: A raw fp32 with BN scale/shift + relu at stage; relu output;
//         fused global_add_pool via spread atomics (batch[] lookup).
#define AP 136   // smem pitch in bf16 (272B rows)

template <int MODE>
__global__ void __launch_bounds__(256, 2) k_gemm_tc(const float* __restrict__ A,
                                                    const __nv_bfloat16* __restrict__ Wh,
                                                    const __nv_bfloat16* __restrict__ Wl,
                                                    const float* __restrict__ bias,
                                                    float* __restrict__ C,
                                                    const int* __restrict__ batch,
                                                    int layer) {
    extern __shared__ char dsm[];
    __nv_bfloat16* a_hi = (__nv_bfloat16*)dsm;            // 64 x AP
    __nv_bfloat16* a_lo = a_hi + 64 * AP;
    __nv_bfloat16* b_hi = a_lo + 64 * AP;                 // 128 x AP
    __nv_bfloat16* b_lo = b_hi + 128 * AP;
    float* s_sum = (float*)(b_lo + 128 * AP);
    float* s_sq  = s_sum + 128;

    const int tid  = threadIdx.x;
    const int lane = tid & 31;
    const int warp = tid >> 5;                 // 0..7
    const int wm = (warp >> 2) * 32;           // 0/32
    const int wn = (warp & 3) * 32;            // 0/32/64/96
    const int m0 = blockIdx.x * 64;

    // ---- stage W (both planes): 2048 uint4 per plane, 256 threads -> 8 iters
#pragma unroll
    for (int j = 0; j < 8; j++) {
        int f = j * 256 + tid;
        int k = f >> 4, q = f & 15;
        size_t off = (size_t)k * D + q * 8;
        *(uint4*)&b_hi[k * AP + q * 8] = *(const uint4*)(Wh + off);
        *(uint4*)&b_lo[k * AP + q * 8] = *(const uint4*)(Wl + off);
    }
    // ---- stage A (64 rows)
    if (MODE == 0) {
#pragma unroll
        for (int j = 0; j < 4; j++) {
            int f = j * 256 + tid;
            int r = f >> 4, q = f & 15;
            size_t off = (size_t)(m0 + r) * D + q * 8;
            *(uint4*)&a_hi[r * AP + q * 8] = *(const uint4*)(g_aggh + off);
            *(uint4*)&a_lo[r * AP + q * 8] = *(const uint4*)(g_aggl + off);
        }
        if (tid < 128) { s_sum[tid] = 0.f; s_sq[tid] = 0.f; }
    } else {
#pragma unroll
        for (int j = 0; j < 8; j++) {
            int f = j * 256 + tid;
            int r = f >> 5, q = f & 31;          // q = float4 index
            int row = m0 + r;
            float4 v = make_float4(0.f, 0.f, 0.f, 0.f);
            if (row < NN) v = *(const float4*)(A + (size_t)row * D + q * 4);
            float4 sc = *(const float4*)(g_scale + q * 4);
            float4 sh = *(const float4*)(g_shift + q * 4);
            v.x = fmaxf(fmaf(v.x, sc.x, sh.x), 0.f);
            v.y = fmaxf(fmaf(v.y, sc.y, sh.y), 0.f);
            v.z = fmaxf(fmaf(v.z, sc.z, sh.z), 0.f);
            v.w = fmaxf(fmaf(v.w, sc.w, sh.w), 0.f);
            __nv_bfloat16 h0, h1, h2, h3, l0, l1, l2, l3;
            split_bf16(v.x, h0, l0); split_bf16(v.y, h1, l1);
            split_bf16(v.z, h2, l2); split_bf16(v.w, h3, l3);
            __nv_bfloat162* ph = (__nv_bfloat162*)(a_hi + r * AP + q * 4);
            __nv_bfloat162* pl = (__nv_bfloat162*)(a_lo + r * AP + q * 4);
            ph[0] = __nv_bfloat162(h0, h1); ph[1] = __nv_bfloat162(h2, h3);
            pl[0] = __nv_bfloat162(l0, l1); pl[1] = __nv_bfloat162(l2, l3);
        }
    }
    __syncthreads();

    float acc[2][4][4];
#pragma unroll
    for (int mf = 0; mf < 2; mf++)
#pragma unroll
        for (int nf = 0; nf < 4; nf++)
#pragma unroll
            for (int i = 0; i < 4; i++) acc[mf][nf][i] = 0.f;

    const int a_row = (lane & 7) + ((lane >> 3) & 1) * 8;
    const int a_kof = (lane >> 4) * 8;
    const int b_kof = (lane & 7) + ((lane >> 3) & 1) * 8;
    const int b_nof = (lane >> 4) * 8;

#pragma unroll
    for (int k = 0; k < D; k += 16) {
        unsigned afh[2][4], afl[2][4];
#pragma unroll
        for (int mf = 0; mf < 2; mf++) {
            unsigned ah = smem_u32(a_hi + (wm + mf * 16 + a_row) * AP + k + a_kof);
            unsigned al = smem_u32(a_lo + (wm + mf * 16 + a_row) * AP + k + a_kof);
            ldsm_x4(ah, afh[mf][0], afh[mf][1], afh[mf][2], afh[mf][3]);
            ldsm_x4(al, afl[mf][0], afl[mf][1], afl[mf][2], afl[mf][3]);
        }
#pragma unroll
        for (int ng = 0; ng < 2; ng++) {
            unsigned bh[4], bl[4];
            int bc = wn + ng * 16 + b_nof;
            ldsm_x4t(smem_u32(b_hi + (k + b_kof) * AP + bc), bh[0], bh[1], bh[2], bh[3]);
            ldsm_x4t(smem_u32(b_lo + (k + b_kof) * AP + bc), bl[0], bl[1], bl[2], bl[3]);
#pragma unroll
            for (int mf = 0; mf < 2; mf++) {
                mma_bf16(acc[mf][2 * ng],     afh[mf], bh);
                mma_bf16(acc[mf][2 * ng],     afh[mf], bl);
                mma_bf16(acc[mf][2 * ng],     afl[mf], bh);
                mma_bf16(acc[mf][2 * ng + 1], afh[mf], bh + 2);
                mma_bf16(acc[mf][2 * ng + 1], afh[mf], bl + 2);
                mma_bf16(acc[mf][2 * ng + 1], afl[mf], bh + 2);
            }
        }
    }

    // ---- epilogue ------------------------------------------------------------
    float st_s[8], st_q[8];
    if (MODE == 0) {
#pragma unroll
        for (int i = 0; i < 8; i++) { st_s[i] = 0.f; st_q[i] = 0.f; }
    }
#pragma unroll
    for (int mf = 0; mf < 2; mf++) {
        int r0 = m0 + wm + mf * 16 + (lane >> 2);
        int g0 = -1, g1 = -1;
        if (MODE == 1) {
            if (r0 < NN)     g0 = batch[r0];
            if (r0 + 8 < NN) g1 = batch[r0 + 8];
        }
#pragma unroll
        for (int nf = 0; nf < 4; nf++) {
            int col = wn + nf * 8 + (lane & 3) * 2;
            float b0 = bias[col], b1 = bias[col + 1];
            float x0 = acc[mf][nf][0] + b0, x1 = acc[mf][nf][1] + b1;
            float x2 = acc[mf][nf][2] + b0, x3 = acc[mf][nf][3] + b1;
            if (MODE == 1) {
                x0 = fmaxf(x0, 0.f); x1 = fmaxf(x1, 0.f);
                x2 = fmaxf(x2, 0.f); x3 = fmaxf(x3, 0.f);
            }
            if (r0 < NN) {
                *(float2*)(C + (size_t)r0 * D + col) = make_float2(x0, x1);
                if (MODE == 0) {
                    st_s[nf * 2]     += x0; st_q[nf * 2]     = fmaf(x0, x0, st_q[nf * 2]);
                    st_s[nf * 2 + 1] += x1; st_q[nf * 2 + 1] = fmaf(x1, x1, st_q[nf * 2 + 1]);
                } else {
                    float* pd = g_pooled + (size_t)g0 * (4 * D) + layer * D + col;
                    atomicAdd(pd, x0); atomicAdd(pd + 1, x1);
                }
            }
            if (r0 + 8 < NN) {
                *(float2*)(C + (size_t)(r0 + 8) * D + col) = make_float2(x2, x3);
                if (MODE == 0) {
                    st_s[nf * 2]     += x2; st_q[nf * 2]     = fmaf(x2, x2, st_q[nf * 2]);
                    st_s[nf * 2 + 1] += x3; st_q[nf * 2 + 1] = fmaf(x3, x3, st_q[nf * 2 + 1]);
                } else {
                    float* pd = g_pooled + (size_t)g1 * (4 * D) + layer * D + col;
                    atomicAdd(pd, x2); atomicAdd(pd + 1, x3);
                }
            }
        }
    }

    if (MODE == 0) {
        // lanes sharing (lane&3) hold the same 8 columns -> butterfly over bits 2..4
#pragma unroll
        for (int off = 4; off < 32; off <<= 1) {
#pragma unroll
            for (int i = 0; i < 8; i++) {
                st_s[i] += __shfl_xor_sync(0xffffffffu, st_s[i], off);
                st_q[i] += __shfl_xor_sync(0xffffffffu, st_q[i], off);
            }
        }
        if (lane < 4) {
#pragma unroll
            for (int nf = 0; nf < 4; nf++) {
                int col = wn + nf * 8 + lane * 2;
                atomicAdd(&s_sum[col],     st_s[nf * 2]);
                atomicAdd(&s_sum[col + 1], st_s[nf * 2 + 1]);
                atomicAdd(&s_sq[col],      st_q[nf * 2]);
                atomicAdd(&s_sq[col + 1],  st_q[nf * 2 + 1]);
            }
        }
        __syncthreads();
        if (tid < 128)      atomicAdd(&g_stats2[tid * 32], s_sum[tid]);
        else if (tid < 256) atomicAdd(&g_stats2[(tid - 128 + 128) * 32], s_sq[tid - 128]);
    }
}

// ---------------- BN finalize (re-zeroes stats for the next layer) -----------
__global__ void k_finalize(const float* __restrict__ gamma, const float* __restrict__ beta) {
    int c = threadIdx.x;
    float mean = g_stats2[c * 32] * (1.f / NN);
    float var  = g_stats2[(128 + c) * 32] * (1.f / NN) - mean * mean;
    float sc   = gamma[c] * rsqrtf(var + BN_EPS);
    g_scale[c] = sc;
    g_shift[c] = fmaf(-mean, sc, beta[c]);
    g_stats2[c * 32] = 0.f;
    g_stats2[(128 + c) * 32] = 0.f;
}

// ---------------- classifier --------------------------------------------------
__global__ void k_cls1(const float* __restrict__ cw1, const float* __restrict__ cb1) {
    int g = blockIdx.x, c = threadIdx.x;
    const float* p = g_pooled + (size_t)g * (4 * D);
    float s = cb1[c];
#pragma unroll 8
    for (int k = 0; k < 4 * D; k++) s = fmaf(p[k], cw1[(size_t)k * D + c], s);
    g_c1[g * D + c] = fmaxf(s, 0.f);
}

__global__ void k_cls2(const float* __restrict__ cw2, const float* __restrict__ cb2) {
    int g = blockIdx.x, c = threadIdx.x;
    const float* p = g_c1 + g * D;
    float s = cb2[c];
#pragma unroll 8
    for (int k = 0; k < D; k++) s = fmaf(p[k], cw2[k * (D / 2) + c], s);
    g_c2[g * (D / 2) + c] = fmaxf(s, 0.f);
}

__global__ void k_cls3(const float* __restrict__ cw3, const float* __restrict__ cb3,
                       float* __restrict__ out) {
    int id = blockIdx.x * blockDim.x + threadIdx.x;
    if (id >= NG * 2) return;
    int g = id >> 1, c = id & 1;
    const float* p = g_c2 + g * (D / 2);
    float s = cb3[c];
#pragma unroll
    for (int k = 0; k < D / 2; k++) s = fmaf(p[k], cw3[k * 2 + c], s);
    out[id] = s;
}

// ---------------- launcher ----------------------------------------------------
extern "C" void kernel_launch(void* const* d_in, const int* in_sizes, int n_in,
                              void* d_out, int out_size) {
    const float* x    = (const float*)d_in[0];
    const int*   ei   = (const int*)  d_in[1];
    const int*   bat  = (const int*)  d_in[2];
    const float* w1   = (const float*)d_in[3];
    const float* b1   = (const float*)d_in[4];
    const float* g1   = (const float*)d_in[5];
    const float* be1  = (const float*)d_in[6];
    const float* w2   = (const float*)d_in[7];
    const float* b2   = (const float*)d_in[8];
    const float* lw1  = (const float*)d_in[9];
    const float* lb1  = (const float*)d_in[10];
    const float* lg1  = (const float*)d_in[11];
    const float* lbe1 = (const float*)d_in[12];
    const float* lw2  = (const float*)d_in[13];
    const float* lb2  = (const float*)d_in[14];
    const float* cw1  = (const float*)d_in[15];
    const float* cb1  = (const float*)d_in[16];
    const float* cw2  = (const float*)d_in[17];
    const float* cb2  = (const float*)d_in[18];
    const float* cw3  = (const float*)d_in[19];
    const float* cb3  = (const float*)d_in[20];
    const int* src = ei;
    const int* dst = ei + NE;

    float *pH1, *pHA, *pHB, *pStats, *pPooled;
    int   *pCnt;
    __nv_bfloat16 *pWh, *pWl, *pAh, *pAl;
    cudaGetSymbolAddress((void**)&pH1,     g_h1);
    cudaGetSymbolAddress((void**)&pHA,     g_hA);
    cudaGetSymbolAddress((void**)&pHB,     g_hB);
    cudaGetSymbolAddress((void**)&pCnt,    g_cnt);
    cudaGetSymbolAddress((void**)&pStats,  g_stats2);
    cudaGetSymbolAddress((void**)&pPooled, g_pooled);
    cudaGetSymbolAddress((void**)&pWh,     g_wh);
    cudaGetSymbolAddress((void**)&pWl,     g_wl);
    cudaGetSymbolAddress((void**)&pAh,     g_aggh);
    cudaGetSymbolAddress((void**)&pAl,     g_aggl);

    // dynamic smem: A 2x64xAP + B 2x128xAP bf16 + 2x128 floats = 105472 B -> 2 CTAs/SM
    const int SMEM_SZ = (2 * 64 + 2 * 128) * AP * 2 + 2 * 128 * 4;
    cudaFuncSetAttribute(k_gemm_tc<0>, cudaFuncAttributeMaxDynamicSharedMemorySize, SMEM_SZ);
    cudaFuncSetAttribute(k_gemm_tc<1>, cudaFuncAttributeMaxDynamicSharedMemorySize, SMEM_SZ);

    cudaMemsetAsync(pCnt,    0, (size_t)NN * sizeof(int));
    cudaMemsetAsync(pStats,  0, 256 * 32 * sizeof(float));
    cudaMemsetAsync(pPooled, 0, (size_t)NG * 4 * D * sizeof(float));
    cudaMemsetAsync(pAh + (size_t)NN * D, 0, (size_t)(NPAD - NN) * D * sizeof(__nv_bfloat16));
    cudaMemsetAsync(pAl + (size_t)NN * D, 0, (size_t)(NPAD - NN) * D * sizeof(__nv_bfloat16));

    k_splitW<<<128, 256>>>(w1, w2, lw1, lw2);
    k_hist<<<2048, 256>>>(dst);
    k_scan<<<1, 1024>>>(bat);
    k_scatter<<<2048, 256>>>(src, dst);

    const int GB = (NN + 63) / 64;   // 1563 tiles
    const float* H = x;
    for (int l = 0; l < 4; l++) {
        const float *B1, *G, *BE, *B2;
        if (l == 0) { B1 = b1; G = g1; BE = be1; B2 = b2; }
        else {
            B1 = lb1 + (l - 1) * D;  G  = lg1 + (l - 1) * D;
            BE = lbe1 + (l - 1) * D; B2 = lb2 + (l - 1) * D;
        }
        const __nv_bfloat16* W1h = pWh + (size_t)(2 * l)     * D * D;
        const __nv_bfloat16* W1l = pWl + (size_t)(2 * l)     * D * D;
        const __nv_bfloat16* W2h = pWh + (size_t)(2 * l + 1) * D * D;
        const __nv_bfloat16* W2l = pWl + (size_t)(2 * l + 1) * D * D;

        k_agg<<<(NN + 3) / 4, 128>>>(H);
        k_gemm_tc<0><<<GB, 256, SMEM_SZ>>>(nullptr, W1h, W1l, B1, pH1, nullptr, l);
        k_finalize<<<1, 128>>>(G, BE);
        float* Hout = (l & 1) ? pHB : pHA;
        k_gemm_tc<1><<<GB, 256, SMEM_SZ>>>(pH1, W2h, W2l, B2, Hout, bat, l);
        H = Hout;
    }

    k_cls1<<<NG, 128>>>(cw1, cb1);
    k_cls2<<<NG, 64>>>(cw2, cb2);
    k_cls3<<<8, 256>>>(cw3, cb3, (float*)d_out);
}